// round 4
// baseline (speedup 1.0000x reference)
#include <cuda_runtime.h>
#include <stdint.h>

#define NN 50000
#define NE 800000
#define IN_DIM 96
#define HID 32
#define OUT_DIM 64

// ---------------- scratch (device globals; no allocation allowed) ----------
__device__ __align__(16) float g_y1[NN * HID];    // x @ W1l (aggregated source)
__device__ __align__(16) float g_z1[NN * HID];    // x @ W1r (self term)
__device__ __align__(16) float g_h[NN * HID];     // hidden activations
__device__ __align__(16) float g_v[NN * HID];     // layer-2 mean agg (pre-scaled)
__device__ int g_deg[NN];
__device__ int g_rowptr[NN + 1];
__device__ int g_cursor[NN];
__device__ int g_srcs[NE];

// ---------------- packed fp32x2 helpers (Blackwell) -------------------------
__device__ __forceinline__ unsigned long long pack2(float lo, float hi) {
    unsigned long long r;
    asm("mov.b64 %0, {%1, %2};" : "=l"(r) : "f"(lo), "f"(hi));
    return r;
}
__device__ __forceinline__ void ffma2(unsigned long long& acc,
                                      unsigned long long a,
                                      unsigned long long b) {
    asm("fma.rn.f32x2 %0, %1, %2, %0;" : "+l"(acc) : "l"(a), "l"(b));
}

// ================= gemm1 (+ deg zeroing): [y1|z1] = x @ [W1l|W1r] ===========
__global__ void __launch_bounds__(128) gemm1_kernel(
    const float* __restrict__ x,
    const float* __restrict__ W1l,
    const float* __restrict__ W1r,
    int n)
{
    __shared__ __align__(16) float sW[IN_DIM][2 * HID];  // 24 KB
    for (int i = threadIdx.x; i < IN_DIM * HID; i += blockDim.x) {
        int k = i / HID, j = i % HID;
        sW[k][j]       = W1l[i];
        sW[k][j + HID] = W1r[i];
    }
    __syncthreads();

    int node = blockIdx.x * blockDim.x + threadIdx.x;
    if (node >= n) return;
    g_deg[node] = 0;   // fused zeroing for the histogram kernel

    unsigned long long acc[32];   // 64 packed fp32 accumulators
#pragma unroll
    for (int j = 0; j < 32; j++) acc[j] = 0ull;

    const float4* xr = (const float4*)(x + (size_t)node * IN_DIM);
#pragma unroll 1
    for (int kq = 0; kq < IN_DIM / 4; kq++) {
        float4 xv = __ldg(&xr[kq]);
        float xs[4] = {xv.x, xv.y, xv.z, xv.w};
#pragma unroll
        for (int kk = 0; kk < 4; kk++) {
            unsigned long long xk2 = pack2(xs[kk], xs[kk]);
            const unsigned long long* wr =
                (const unsigned long long*)sW[kq * 4 + kk];
#pragma unroll
            for (int j = 0; j < 32; j += 2) {
                ulonglong2 w = *(const ulonglong2*)&wr[j];
                ffma2(acc[j],     xk2, w.x);
                ffma2(acc[j + 1], xk2, w.y);
            }
        }
    }

    // cols 0..31 -> y1 (acc[0..15]); cols 32..63 -> z1 (acc[16..31])
    ulonglong2* y = (ulonglong2*)(g_y1 + (size_t)node * HID);
    ulonglong2* z = (ulonglong2*)(g_z1 + (size_t)node * HID);
#pragma unroll
    for (int j = 0; j < 8; j++) {
        y[j] = make_ulonglong2(acc[2 * j],      acc[2 * j + 1]);
        z[j] = make_ulonglong2(acc[16 + 2 * j], acc[16 + 2 * j + 1]);
    }
}

// ================= CSR build ================================================
__global__ void hist_kernel(const int* __restrict__ dst, int E) {
    int e = blockIdx.x * blockDim.x + threadIdx.x;
    if (e < E) atomicAdd(&g_deg[dst[e]], 1);
}

#define SCAN_IT 49   // 1024 * 49 = 50176 >= NN
__global__ void __launch_bounds__(1024) scan_kernel() {
    int t = threadIdx.x;
    int lane = t & 31, warp = t >> 5;
    int base = t * SCAN_IT;

    int s = 0;
#pragma unroll 1
    for (int j = 0; j < SCAN_IT; j++) {
        int idx = base + j;
        if (idx < NN) s += g_deg[idx];
    }
    // block exclusive scan of per-thread sums
    int incl = s;
#pragma unroll
    for (int o = 1; o < 32; o <<= 1) {
        int v = __shfl_up_sync(~0u, incl, o);
        if (lane >= o) incl += v;
    }
    __shared__ int wtot[32];
    if (lane == 31) wtot[warp] = incl;
    __syncthreads();
    if (warp == 0) {
        int v = wtot[lane];
        int iv = v;
#pragma unroll
        for (int o = 1; o < 32; o <<= 1) {
            int u = __shfl_up_sync(~0u, iv, o);
            if (lane >= o) iv += u;
        }
        wtot[lane] = iv - v;   // exclusive warp offset
    }
    __syncthreads();

    int run = wtot[warp] + incl - s;   // exclusive prefix for this thread
#pragma unroll 1
    for (int j = 0; j < SCAN_IT; j++) {
        int idx = base + j;
        if (idx < NN) {
            g_rowptr[idx] = run;
            g_cursor[idx] = run;
            run += g_deg[idx];
        }
    }
    if (t == 1023) g_rowptr[NN] = run;
}

__global__ void fill_kernel(const int* __restrict__ ei, int E) {
    int e = blockIdx.x * blockDim.x + threadIdx.x;
    if (e >= E) return;
    int src = ei[e];
    int dst = ei[E + e];
    int pos = atomicAdd(&g_cursor[dst], 1);
    g_srcs[pos] = src;
}

// ================= gather layer 1 (fused combine+relu) ======================
// warp per node; lane = feature. 32 indices per coalesced load, shfl-broadcast,
// fully unrolled uniformly-predicated body -> all feature loads independent.
__global__ void __launch_bounds__(256) gather1_kernel(const float* __restrict__ b1) {
    int gtid = blockIdx.x * blockDim.x + threadIdx.x;
    int node = gtid >> 5;
    int lane = gtid & 31;
    if (node >= NN) return;

    int rs = g_rowptr[node];
    int re = g_rowptr[node + 1];

    float acc = 0.f;
    int i = rs;
    while (i < re) {
        int n = re - i;                      // uniform across warp
        int m = n < 32 ? n : 32;
        int ii = i + (lane < m ? lane : m - 1);
        int idx = __ldg(&g_srcs[ii]);
#pragma unroll
        for (int j = 0; j < 32; j++) {
            if (j < m) {                     // uniform predicate
                int s = __shfl_sync(~0u, idx, j);
                acc += __ldg(&g_y1[(size_t)s * HID + lane]);
            }
        }
        i += m;
    }

    float deg  = (float)(re - rs);
    float invc = 1.0f / fmaxf(deg, 1.0f);
    float hval = fmaxf(
        fmaf(acc, invc, g_z1[(size_t)node * HID + lane] + __ldg(&b1[lane])), 0.f);
    g_h[(size_t)node * HID + lane] = hval;
}

// ================= gather layer 2 ===========================================
__global__ void __launch_bounds__(256) gather2_kernel() {
    int gtid = blockIdx.x * blockDim.x + threadIdx.x;
    int node = gtid >> 5;
    int lane = gtid & 31;
    if (node >= NN) return;

    int rs = g_rowptr[node];
    int re = g_rowptr[node + 1];

    float acc = 0.f;
    int i = rs;
    while (i < re) {
        int n = re - i;
        int m = n < 32 ? n : 32;
        int ii = i + (lane < m ? lane : m - 1);
        int idx = __ldg(&g_srcs[ii]);
#pragma unroll
        for (int j = 0; j < 32; j++) {
            if (j < m) {
                int s = __shfl_sync(~0u, idx, j);
                acc += __ldg(&g_h[(size_t)s * HID + lane]);
            }
        }
        i += m;
    }

    float invc = 1.0f / fmaxf((float)(re - rs), 1.0f);
    g_v[(size_t)node * HID + lane] = acc * invc;
}

// ================= layer 2: out = v@W2l + h@W2r + b2 ========================
__global__ void __launch_bounds__(128) layer2_kernel(
    const float* __restrict__ W2l,
    const float* __restrict__ W2r,
    const float* __restrict__ b2,
    float* __restrict__ out,
    int n)
{
    __shared__ __align__(16) float sW[2 * HID][OUT_DIM];  // 16 KB; rows 0..31 = W2l
    for (int i = threadIdx.x; i < HID * OUT_DIM; i += blockDim.x) {
        int k = i / OUT_DIM, j = i % OUT_DIM;
        sW[k][j]       = W2l[i];
        sW[k + HID][j] = W2r[i];
    }
    __syncthreads();

    int node = blockIdx.x * blockDim.x + threadIdx.x;
    if (node >= n) return;

    float vv[64];
#pragma unroll
    for (int k = 0; k < HID; k += 4) {
        float4 a = *(const float4*)&g_v[(size_t)node * HID + k];
        vv[k + 0] = a.x; vv[k + 1] = a.y; vv[k + 2] = a.z; vv[k + 3] = a.w;
        float4 hh = *(const float4*)&g_h[(size_t)node * HID + k];
        vv[HID + k + 0] = hh.x; vv[HID + k + 1] = hh.y;
        vv[HID + k + 2] = hh.z; vv[HID + k + 3] = hh.w;
    }

    unsigned long long acc[32];   // 64 packed outputs (init = bias)
    const unsigned long long* b2p = (const unsigned long long*)b2;
#pragma unroll
    for (int j = 0; j < 32; j++) acc[j] = __ldg(&b2p[j]);

#pragma unroll 1
    for (int k = 0; k < 64; k++) {
        unsigned long long vk2 = pack2(vv[k], vv[k]);
        const unsigned long long* wr = (const unsigned long long*)sW[k];
#pragma unroll
        for (int j = 0; j < 32; j += 2) {
            ulonglong2 w = *(const ulonglong2*)&wr[j];
            ffma2(acc[j],     vk2, w.x);
            ffma2(acc[j + 1], vk2, w.y);
        }
    }

    ulonglong2* op = (ulonglong2*)(out + (size_t)node * OUT_DIM);
#pragma unroll
    for (int j = 0; j < 16; j++)
        op[j] = make_ulonglong2(acc[2 * j], acc[2 * j + 1]);
}

// ================= launch ===================================================
extern "C" void kernel_launch(void* const* d_in, const int* in_sizes, int n_in,
                              void* d_out, int out_size)
{
    const float* x   = (const float*)d_in[0];
    const int*   ei  = (const int*)d_in[1];   // int32 (JAX x64 disabled)
    const float* W1l = (const float*)d_in[2];
    const float* W1r = (const float*)d_in[3];
    const float* b1  = (const float*)d_in[4];
    const float* W2l = (const float*)d_in[5];
    const float* W2r = (const float*)d_in[6];
    const float* b2  = (const float*)d_in[7];
    float*       out = (float*)d_out;

    int n = in_sizes[0] / IN_DIM;   // 50000
    int E = in_sizes[1] / 2;        // 800000

    // 1) layer-1 GEMM (also zeroes g_deg)
    gemm1_kernel<<<(n + 127) / 128, 128>>>(x, W1l, W1r, n);
    // 2-4) CSR build
    hist_kernel<<<(E + 511) / 512, 512>>>(ei + E, E);
    scan_kernel<<<1, 1024>>>();
    fill_kernel<<<(E + 511) / 512, 512>>>(ei, E);
    // 5) gather + combine + relu -> h
    {
        long long work = (long long)NN * 32;
        gather1_kernel<<<(int)((work + 255) / 256), 256>>>(b1);
    }
    // 6) gather -> v (pre-scaled mean)
    {
        long long work = (long long)NN * 32;
        gather2_kernel<<<(int)((work + 255) / 256), 256>>>();
    }
    // 7) output GEMV
    layer2_kernel<<<(n + 127) / 128, 128>>>(W2l, W2r, b2, out, n);
}

// round 6
// speedup vs baseline: 1.9661x; 1.9661x over previous
#include <cuda_runtime.h>
#include <stdint.h>

#define NN 50000
#define NE 800000
#define IN_DIM 96
#define HID 32
#define OUT_DIM 64

// ---------------- scratch (device globals; no allocation allowed) ----------
__device__ __align__(16) float g_y1[NN * HID];    // x @ W1l   (to be aggregated)
__device__ __align__(16) float g_z1[NN * HID];    // x @ W1r   (self term)
__device__ __align__(16) float g_agg1[NN * HID];  // scatter accum, layer 1
__device__ __align__(16) float g_h[NN * HID];     // hidden activations
__device__ __align__(16) float g_agg2[NN * HID];  // scatter accum, layer 2
__device__ float g_cnt[NN];
__device__ float g_invc[NN];

// ---------------- packed fp32x2 helpers (Blackwell) -------------------------
__device__ __forceinline__ unsigned long long pack2(float lo, float hi) {
    unsigned long long r;
    asm("mov.b64 %0, {%1, %2};" : "=l"(r) : "f"(lo), "f"(hi));
    return r;
}
__device__ __forceinline__ void ffma2(unsigned long long& acc,
                                      unsigned long long a,
                                      unsigned long long b) {
    asm("fma.rn.f32x2 %0, %1, %2, %0;" : "+l"(acc) : "l"(a), "l"(b));
}

// ======= gemm1 (+ fused accumulator zeroing): [y1|z1] = x @ [W1l|W1r] =======
__global__ void __launch_bounds__(128) gemm1_kernel(
    const float* __restrict__ x,
    const float* __restrict__ W1l,
    const float* __restrict__ W1r,
    int n)
{
    __shared__ __align__(16) float sW[IN_DIM][2 * HID];  // 24 KB
    for (int i = threadIdx.x; i < IN_DIM * HID; i += blockDim.x) {
        int k = i / HID, j = i % HID;
        sW[k][j]       = W1l[i];
        sW[k][j + HID] = W1r[i];
    }
    __syncthreads();

    int node = blockIdx.x * blockDim.x + threadIdx.x;
    if (node >= n) return;

    // fused zeroing of the scatter accumulators + counts (drains under FMAs)
    {
        float4 z4 = make_float4(0.f, 0.f, 0.f, 0.f);
        float4* a1 = (float4*)(g_agg1 + (size_t)node * HID);
        float4* a2 = (float4*)(g_agg2 + (size_t)node * HID);
#pragma unroll
        for (int j = 0; j < 8; j++) { a1[j] = z4; a2[j] = z4; }
        g_cnt[node] = 0.f;
    }

    unsigned long long acc[32];   // 64 packed fp32 accumulators
#pragma unroll
    for (int j = 0; j < 32; j++) acc[j] = 0ull;

    const float4* xr = (const float4*)(x + (size_t)node * IN_DIM);
#pragma unroll 1
    for (int kq = 0; kq < IN_DIM / 4; kq++) {
        float4 xv = __ldg(&xr[kq]);
        float xs[4] = {xv.x, xv.y, xv.z, xv.w};
#pragma unroll
        for (int kk = 0; kk < 4; kk++) {
            unsigned long long xk2 = pack2(xs[kk], xs[kk]);
            const unsigned long long* wr =
                (const unsigned long long*)sW[kq * 4 + kk];
#pragma unroll
            for (int j = 0; j < 32; j += 2) {
                ulonglong2 w = *(const ulonglong2*)&wr[j];
                ffma2(acc[j],     xk2, w.x);
                ffma2(acc[j + 1], xk2, w.y);
            }
        }
    }

    // cols 0..31 -> y1 (acc[0..15]); cols 32..63 -> z1 (acc[16..31])
    ulonglong2* y = (ulonglong2*)(g_y1 + (size_t)node * HID);
    ulonglong2* z = (ulonglong2*)(g_z1 + (size_t)node * HID);
#pragma unroll
    for (int j = 0; j < 8; j++) {
        y[j] = make_ulonglong2(acc[2 * j],      acc[2 * j + 1]);
        z[j] = make_ulonglong2(acc[16 + 2 * j], acc[16 + 2 * j + 1]);
    }
}

// ---------------- edge scatter: agg[dst] += feat[src] (dim 32) -------------
// 8 threads per edge, one float4 each -> one 128B line gather + v4 red.
// (unchanged from the 110.7us R2 kernel)
__global__ void __launch_bounds__(256) scatter_kernel(
    const int* __restrict__ ei, int E, int layer)
{
    int tid = blockIdx.x * blockDim.x + threadIdx.x;
    int e = tid >> 3;
    int l = tid & 7;
    if (e >= E) return;

    int src = ei[e];
    int dst = ei[E + e];

    const float* feat = (layer == 0) ? g_y1 : g_h;
    float*       agg  = (layer == 0) ? g_agg1 : g_agg2;

    float4 v = *(const float4*)(feat + (size_t)src * HID + l * 4);
    float* p = agg + (size_t)dst * HID + l * 4;
    asm volatile("red.global.add.v4.f32 [%0], {%1,%2,%3,%4};"
                 :: "l"(p), "f"(v.x), "f"(v.y), "f"(v.z), "f"(v.w)
                 : "memory");
    if (layer == 0 && l == 0) atomicAdd(g_cnt + dst, 1.0f);
}

// ---------------- combine layer 1: h = relu(agg1/cnt + z1 + b1) ------------
__global__ void combine1_kernel(const float* __restrict__ b1, int n) {
    int tid = blockIdx.x * blockDim.x + threadIdx.x;
    int node = tid >> 3;
    int q = tid & 7;
    if (node >= n) return;

    float c = g_cnt[node];
    float invc = 1.0f / fmaxf(c, 1.0f);
    if (q == 0) g_invc[node] = invc;

    size_t off = (size_t)node * HID + q * 4;
    float4 a  = *(const float4*)&g_agg1[off];
    float4 z  = *(const float4*)&g_z1[off];
    float4 bb = *(const float4*)&b1[q * 4];
    float4 h;
    h.x = fmaxf(fmaf(a.x, invc, z.x + bb.x), 0.f);
    h.y = fmaxf(fmaf(a.y, invc, z.y + bb.y), 0.f);
    h.z = fmaxf(fmaf(a.z, invc, z.z + bb.z), 0.f);
    h.w = fmaxf(fmaf(a.w, invc, z.w + bb.w), 0.f);
    *(float4*)&g_h[off] = h;
}

// ---------------- layer 2: out = (agg2/cnt)@W2l + h@W2r + b2 ---------------
__global__ void __launch_bounds__(128) layer2_kernel(
    const float* __restrict__ W2l,
    const float* __restrict__ W2r,
    const float* __restrict__ b2,
    float* __restrict__ out,
    int n)
{
    __shared__ __align__(16) float sW[2 * HID][OUT_DIM];  // 16 KB; rows 0..31 = W2l
    for (int i = threadIdx.x; i < HID * OUT_DIM; i += blockDim.x) {
        int k = i / OUT_DIM, j = i % OUT_DIM;
        sW[k][j]       = W2l[i];
        sW[k + HID][j] = W2r[i];
    }
    __syncthreads();

    int node = blockIdx.x * blockDim.x + threadIdx.x;
    if (node >= n) return;

    float invc = g_invc[node];
    float vv[64];
#pragma unroll
    for (int k = 0; k < HID; k += 4) {
        float4 a = *(const float4*)&g_agg2[(size_t)node * HID + k];
        vv[k + 0] = a.x * invc;
        vv[k + 1] = a.y * invc;
        vv[k + 2] = a.z * invc;
        vv[k + 3] = a.w * invc;
        float4 hh = *(const float4*)&g_h[(size_t)node * HID + k];
        vv[HID + k + 0] = hh.x; vv[HID + k + 1] = hh.y;
        vv[HID + k + 2] = hh.z; vv[HID + k + 3] = hh.w;
    }

    unsigned long long acc[32];   // 64 packed outputs (init = bias)
    const unsigned long long* b2p = (const unsigned long long*)b2;
#pragma unroll
    for (int j = 0; j < 32; j++) acc[j] = __ldg(&b2p[j]);

#pragma unroll 1
    for (int k = 0; k < 64; k++) {
        unsigned long long vk2 = pack2(vv[k], vv[k]);
        const unsigned long long* wr = (const unsigned long long*)sW[k];
#pragma unroll
        for (int j = 0; j < 32; j += 2) {
            ulonglong2 w = *(const ulonglong2*)&wr[j];
            ffma2(acc[j],     vk2, w.x);
            ffma2(acc[j + 1], vk2, w.y);
        }
    }

    ulonglong2* op = (ulonglong2*)(out + (size_t)node * OUT_DIM);
#pragma unroll
    for (int j = 0; j < 16; j++)
        op[j] = make_ulonglong2(acc[2 * j], acc[2 * j + 1]);
}

// ================= launch ===================================================
extern "C" void kernel_launch(void* const* d_in, const int* in_sizes, int n_in,
                              void* d_out, int out_size)
{
    const float* x   = (const float*)d_in[0];
    const int*   ei  = (const int*)d_in[1];   // int32 (JAX x64 disabled)
    const float* W1l = (const float*)d_in[2];
    const float* W1r = (const float*)d_in[3];
    const float* b1  = (const float*)d_in[4];
    const float* W2l = (const float*)d_in[5];
    const float* W2r = (const float*)d_in[6];
    const float* b2  = (const float*)d_in[7];
    float*       out = (float*)d_out;

    int n = in_sizes[0] / IN_DIM;   // 50000
    int E = in_sizes[1] / 2;        // 800000

    // 1) fused layer-1 GEMM (+ zero accumulators/counts)
    gemm1_kernel<<<(n + 127) / 128, 128>>>(x, W1l, W1r, n);
    // 2) scatter y1 into agg1 (+ degree counts)
    {
        long long work = (long long)E * 8;
        scatter_kernel<<<(int)((work + 255) / 256), 256>>>(ei, E, 0);
    }
    // 3) h = relu(agg1/cnt + z1 + b1)
    combine1_kernel<<<(n * 8 + 255) / 256, 256>>>(b1, n);
    // 4) scatter h into agg2
    {
        long long work = (long long)E * 8;
        scatter_kernel<<<(int)((work + 255) / 256), 256>>>(ei, E, 1);
    }
    // 5) out = (agg2/cnt)@W2l + h@W2r + b2
    layer2_kernel<<<(n + 127) / 128, 128>>>(W2l, W2r, b2, out, n);
}

// round 9
// speedup vs baseline: 2.1481x; 1.0926x over previous
#include <cuda_runtime.h>
#include <stdint.h>

#define NN 50000
#define NE 800000
#define IN_DIM 96
#define HID 32
#define OUT_DIM 64
#define EPT 4   // edges per thread in scatter (MLP)

// ---------------- scratch (device globals; no allocation allowed) ----------
__device__ __align__(16) float g_y1[NN * HID];    // x @ W1l   (to be aggregated)
__device__ __align__(16) float g_z1[NN * HID];    // x @ W1r   (self term)
__device__ __align__(16) float g_agg1[NN * HID];  // scatter accum, layer 1
__device__ __align__(16) float g_h[NN * HID];     // hidden activations
__device__ __align__(16) float g_agg2[NN * HID];  // scatter accum, layer 2
__device__ float g_cnt[NN];
__device__ float g_invc[NN];

// ---------------- zero the accumulators (coalesced, proven) ----------------
__global__ void zero_bufs() {
    int i = blockIdx.x * blockDim.x + threadIdx.x;
    const int nv4 = NN * HID / 4;
    if (i < nv4) {
        ((float4*)g_agg1)[i] = make_float4(0.f, 0.f, 0.f, 0.f);
        ((float4*)g_agg2)[i] = make_float4(0.f, 0.f, 0.f, 0.f);
    }
    if (i < NN) g_cnt[i] = 0.f;
}

// ---------------- layer-1 GEMM: [y1 | z1] = x @ [W1l | W1r] ----------------
// thread-per-node, 64 fp32 accumulators, weights broadcast from smem. (R2)
__global__ void __launch_bounds__(128) gemm1_kernel(
    const float* __restrict__ x,
    const float* __restrict__ W1l,
    const float* __restrict__ W1r,
    int n)
{
    __shared__ float sW[IN_DIM][2 * HID];  // [96][64] = 24 KB
    for (int i = threadIdx.x; i < IN_DIM * HID; i += blockDim.x) {
        int k = i / HID, j = i % HID;
        sW[k][j]       = W1l[i];
        sW[k][j + HID] = W1r[i];
    }
    __syncthreads();

    int node = blockIdx.x * blockDim.x + threadIdx.x;
    if (node >= n) return;

    float acc[64];
#pragma unroll
    for (int j = 0; j < 64; j++) acc[j] = 0.f;

    const float4* xr = (const float4*)(x + (size_t)node * IN_DIM);
#pragma unroll 1
    for (int kq = 0; kq < IN_DIM / 4; kq++) {
        float4 xv = __ldg(&xr[kq]);
        float xs[4] = {xv.x, xv.y, xv.z, xv.w};
#pragma unroll
        for (int kk = 0; kk < 4; kk++) {
            float xk = xs[kk];
            const float* wr = sW[kq * 4 + kk];
#pragma unroll
            for (int j = 0; j < 64; j += 4) {
                float4 w = *(const float4*)&wr[j];
                acc[j + 0] += xk * w.x;
                acc[j + 1] += xk * w.y;
                acc[j + 2] += xk * w.z;
                acc[j + 3] += xk * w.w;
            }
        }
    }

    float* y = g_y1 + (size_t)node * HID;
    float* z = g_z1 + (size_t)node * HID;
#pragma unroll
    for (int j = 0; j < HID; j += 4) {
        *(float4*)&y[j] = make_float4(acc[j], acc[j + 1], acc[j + 2], acc[j + 3]);
        *(float4*)&z[j] = make_float4(acc[HID + j], acc[HID + j + 1],
                                      acc[HID + j + 2], acc[HID + j + 3]);
    }
}

// ---------------- edge scatter: agg[dst] += feat[src] (dim 32) -------------
// 8 threads per edge-group lane, EPT independent edges per thread -> MLP=EPT.
// Per edge: one 128B line gather + one v4 red (identical byte/atomic counts
// to the R2 version; only the per-thread chain structure changed).
__global__ void __launch_bounds__(256) scatter_kernel(
    const int* __restrict__ ei, int E, int layer)
{
    int tid = blockIdx.x * blockDim.x + threadIdx.x;
    int g = tid >> 3;           // edge-group id
    int l = tid & 7;            // lane within edge (feature quad)
    int G = (E + EPT - 1) / EPT;
    if (g >= G) return;

    const float* feat = (layer == 0) ? g_y1 : g_h;
    float*       agg  = (layer == 0) ? g_agg1 : g_agg2;

    int  e[EPT];
    bool valid[EPT];
    int  src[EPT], dst[EPT];
#pragma unroll
    for (int k = 0; k < EPT; k++) {
        e[k] = g + k * G;
        valid[k] = (e[k] < E);
    }
    // batch the index loads (independent)
#pragma unroll
    for (int k = 0; k < EPT; k++) {
        if (valid[k]) {
            src[k] = __ldg(&ei[e[k]]);
            dst[k] = __ldg(&ei[E + e[k]]);
        }
    }
    // batch the feature gathers (independent 128B lines)
    float4 v[EPT];
#pragma unroll
    for (int k = 0; k < EPT; k++) {
        if (valid[k])
            v[k] = *(const float4*)(feat + (size_t)src[k] * HID + l * 4);
    }
    // fire the reductions
#pragma unroll
    for (int k = 0; k < EPT; k++) {
        if (valid[k]) {
            float* p = agg + (size_t)dst[k] * HID + l * 4;
            asm volatile("red.global.add.v4.f32 [%0], {%1,%2,%3,%4};"
                         :: "l"(p), "f"(v[k].x), "f"(v[k].y), "f"(v[k].z), "f"(v[k].w)
                         : "memory");
            if (layer == 0 && l == 0) atomicAdd(g_cnt + dst[k], 1.0f);
        }
    }
}

// ---------------- combine layer 1: h = relu(agg1/cnt + z1 + b1) ------------
__global__ void combine1_kernel(const float* __restrict__ b1, int n) {
    int tid = blockIdx.x * blockDim.x + threadIdx.x;
    int node = tid >> 3;
    int q = tid & 7;
    if (node >= n) return;

    float c = g_cnt[node];
    float invc = 1.0f / fmaxf(c, 1.0f);
    if (q == 0) g_invc[node] = invc;

    size_t off = (size_t)node * HID + q * 4;
    float4 a  = *(const float4*)&g_agg1[off];
    float4 z  = *(const float4*)&g_z1[off];
    float4 bb = *(const float4*)&b1[q * 4];
    float4 h;
    h.x = fmaxf(fmaf(a.x, invc, z.x + bb.x), 0.f);
    h.y = fmaxf(fmaf(a.y, invc, z.y + bb.y), 0.f);
    h.z = fmaxf(fmaf(a.z, invc, z.z + bb.z), 0.f);
    h.w = fmaxf(fmaf(a.w, invc, z.w + bb.w), 0.f);
    *(float4*)&g_h[off] = h;
}

// ---------------- layer 2: out = (agg2/cnt)@W2l + h@W2r + b2 ---------------
// thread-per-node GEMV on concat(agg2*invc, h) with stacked 64x64 weights. (R2)
__global__ void __launch_bounds__(128) layer2_kernel(
    const float* __restrict__ W2l,
    const float* __restrict__ W2r,
    const float* __restrict__ b2,
    float* __restrict__ out,
    int n)
{
    __shared__ float sW[2 * HID][OUT_DIM];  // 64x64 = 16 KB; rows 0..31 = W2l
    for (int i = threadIdx.x; i < HID * OUT_DIM; i += blockDim.x) {
        int k = i / OUT_DIM, j = i % OUT_DIM;
        sW[k][j]       = W2l[i];
        sW[k + HID][j] = W2r[i];
    }
    __syncthreads();

    int node = blockIdx.x * blockDim.x + threadIdx.x;
    if (node >= n) return;

    float invc = g_invc[node];
    float v[64];
#pragma unroll
    for (int k = 0; k < HID; k += 4) {
        float4 a = *(const float4*)&g_agg2[(size_t)node * HID + k];
        v[k + 0] = a.x * invc;
        v[k + 1] = a.y * invc;
        v[k + 2] = a.z * invc;
        v[k + 3] = a.w * invc;
        float4 hh = *(const float4*)&g_h[(size_t)node * HID + k];
        v[HID + k + 0] = hh.x;
        v[HID + k + 1] = hh.y;
        v[HID + k + 2] = hh.z;
        v[HID + k + 3] = hh.w;
    }

#pragma unroll 1
    for (int j = 0; j < OUT_DIM; j += 4) {
        float4 bb = *(const float4*)&b2[j];
        float a0 = bb.x, a1 = bb.y, a2 = bb.z, a3 = bb.w;
#pragma unroll
        for (int k = 0; k < 64; k++) {
            float4 w = *(const float4*)&sW[k][j];
            a0 += v[k] * w.x;
            a1 += v[k] * w.y;
            a2 += v[k] * w.z;
            a3 += v[k] * w.w;
        }
        *(float4*)&out[(size_t)node * OUT_DIM + j] = make_float4(a0, a1, a2, a3);
    }
}

// ---------------- launch --------------------------------------------------
extern "C" void kernel_launch(void* const* d_in, const int* in_sizes, int n_in,
                              void* d_out, int out_size)
{
    const float* x   = (const float*)d_in[0];
    const int*   ei  = (const int*)d_in[1];   // int32 (JAX x64 disabled)
    const float* W1l = (const float*)d_in[2];
    const float* W1r = (const float*)d_in[3];
    const float* b1  = (const float*)d_in[4];
    const float* W2l = (const float*)d_in[5];
    const float* W2r = (const float*)d_in[6];
    const float* b2  = (const float*)d_in[7];
    float*       out = (float*)d_out;

    int n = in_sizes[0] / IN_DIM;   // 50000
    int E = in_sizes[1] / 2;        // 800000

    // 1) zero accumulators + counts
    {
        int tot = NN * HID / 4;
        zero_bufs<<<(tot + 255) / 256, 256>>>();
    }
    // 2) fused layer-1 GEMM: y1 = x@W1l, z1 = x@W1r
    gemm1_kernel<<<(n + 127) / 128, 128>>>(x, W1l, W1r, n);
    // 3) scatter y1 into agg1 (+ degree counts), MLP=EPT
    {
        int G = (E + EPT - 1) / EPT;
        long long work = (long long)G * 8;
        scatter_kernel<<<(int)((work + 255) / 256), 256>>>(ei, E, 0);
    }
    // 4) h = relu(agg1/cnt + z1 + b1)
    combine1_kernel<<<(n * 8 + 255) / 256, 256>>>(b1, n);
    // 5) scatter h into agg2, MLP=EPT
    {
        int G = (E + EPT - 1) / EPT;
        long long work = (long long)G * 8;
        scatter_kernel<<<(int)((work + 255) / 256), 256>>>(ei, E, 1);
    }
    // 6) out = (agg2/cnt)@W2l + h@W2r + b2
    layer2_kernel<<<(n + 127) / 128, 128>>>(W2l, W2r, b2, out, n);
}